// round 16
// baseline (speedup 1.0000x reference)
#include <cuda_runtime.h>
#include <cstdint>

// Problem constants
#define NN 100000
#define EE 3200000
#define FIN 512
#define HH 16
#define CC 40

// ---------------- scratch (device globals, referenced DIRECTLY) -------------
__device__ float g_h0[NN * HH];
__device__ float g_h1[NN * HH];
__device__ float g_agg[NN * HH];
__device__ float g_deg[NN];
__device__ float g_dinv[NN];
__device__ int   g_cnt[NN];
__device__ int   g_offs[NN];
__device__ int   g_cur[NN];
__device__ int2  g_edge[EE];     // (src, nrm-bits) compact CSC
__device__ int   g_total;

// ---------------- packed f32x2 helpers --------------------------------------
__device__ __forceinline__ unsigned long long pack2(float v) {
    unsigned long long r;
    asm("mov.b64 %0, {%1,%1};" : "=l"(r) : "f"(v));
    return r;
}
__device__ __forceinline__ void fma2(unsigned long long& acc,
                                     unsigned long long a, unsigned long long b) {
    asm("fma.rn.f32x2 %0, %1, %2, %0;" : "+l"(acc) : "l"(a), "l"(b));
}
__device__ __forceinline__ void add2(unsigned long long& a, unsigned long long b) {
    asm("add.rn.f32x2 %0, %0, %1;" : "+l"(a) : "l"(b));
}
__device__ __forceinline__ float lo2(unsigned long long v) {
    return __uint_as_float((unsigned)(v & 0xffffffffu));
}
__device__ __forceinline__ float hi2(unsigned long long v) {
    return __uint_as_float((unsigned)(v >> 32));
}

// ---------------- fc1: g_h0 = relu(x @ W_first + b_first) -------------------
// 2 rows per warp (register sweet spot: ~75 regs), f32x2, stride-18 W smem
// (conflict-free LDS.64 at k = lane + 32t), coalesced x loads.
#define FC1_TB 256
#define WST 18
__global__ void __launch_bounds__(FC1_TB)
k_fc1(const float* __restrict__ x, const float* __restrict__ W,
      const float* __restrict__ b) {
    __shared__ float Wsh[FIN * WST];   // 36.9 KB
    for (int i = threadIdx.x; i < FIN * HH; i += FC1_TB) {
        int k = i >> 4, j = i & 15;
        Wsh[k * WST + j] = W[i];
    }
    __syncthreads();

    int warp = threadIdx.x >> 5, lane = threadIdx.x & 31;
    int row0 = blockIdx.x * 16 + warp * 2;   // 8 warps x 2 rows
    if (row0 >= NN) return;

    unsigned long long acc0[8], acc1[8];
#pragma unroll
    for (int p = 0; p < 8; p++) { acc0[p] = 0ull; acc1[p] = 0ull; }

#pragma unroll
    for (int half = 0; half < 2; half++) {
        float xv0[8], xv1[8];
        const float* xr0 = x + (size_t)row0 * FIN + half * 256;
        const float* xr1 = xr0 + FIN;
#pragma unroll
        for (int t = 0; t < 8; t++) {
            xv0[t] = xr0[lane + 32 * t];
            xv1[t] = xr1[lane + 32 * t];
        }
#pragma unroll
        for (int t = 0; t < 8; t++) {
            int k = lane + 32 * t + half * 256;
            const unsigned long long* wr = (const unsigned long long*)(Wsh + k * WST);
            unsigned long long w[8];
#pragma unroll
            for (int p = 0; p < 8; p++) w[p] = wr[p];
            unsigned long long p0 = pack2(xv0[t]);
            unsigned long long p1 = pack2(xv1[t]);
#pragma unroll
            for (int p = 0; p < 8; p++) {
                fma2(acc0[p], p0, w[p]);
                fma2(acc1[p], p1, w[p]);
            }
        }
    }

    // warp tree-reduce packed pairs for both rows
#pragma unroll
    for (int p = 0; p < 8; p++) {
        unsigned long long v0 = acc0[p], v1 = acc1[p];
#pragma unroll
        for (int s = 16; s > 0; s >>= 1) {
            add2(v0, __shfl_xor_sync(0xffffffffu, v0, s));
            add2(v1, __shfl_xor_sync(0xffffffffu, v1, s));
        }
        acc0[p] = v0; acc1[p] = v1;
    }
    if (lane == 0) {
        float bb[16];
#pragma unroll
        for (int j = 0; j < 16; j++) bb[j] = __ldg(&b[j]);
        float4* d0 = (float4*)(g_h0 + (size_t)row0 * HH);
        float4* d1 = (float4*)(g_h0 + (size_t)(row0 + 1) * HH);
#pragma unroll
        for (int q = 0; q < 4; q++) {
            d0[q] = make_float4(
                fmaxf(lo2(acc0[2 * q])     + bb[4 * q + 0], 0.0f),
                fmaxf(hi2(acc0[2 * q])     + bb[4 * q + 1], 0.0f),
                fmaxf(lo2(acc0[2 * q + 1]) + bb[4 * q + 2], 0.0f),
                fmaxf(hi2(acc0[2 * q + 1]) + bb[4 * q + 3], 0.0f));
            d1[q] = make_float4(
                fmaxf(lo2(acc1[2 * q])     + bb[4 * q + 0], 0.0f),
                fmaxf(hi2(acc1[2 * q])     + bb[4 * q + 1], 0.0f),
                fmaxf(lo2(acc1[2 * q + 1]) + bb[4 * q + 2], 0.0f),
                fmaxf(hi2(acc1[2 * q + 1]) + bb[4 * q + 3], 0.0f));
        }
    }
}

// ---------------- init ------------------------------------------------------
__global__ void k_init() {
    int i = blockIdx.x * blockDim.x + threadIdx.x;
    if (i < NN) { g_deg[i] = 1.0f; g_cnt[i] = 0; }
    if (i == 0) g_total = 0;
}

// ---------------- degree + histogram (edge_index is int32) ------------------
__global__ void k_deg(const int* __restrict__ ei, const float* __restrict__ ew) {
    int e = blockIdx.x * blockDim.x + threadIdx.x;
    if (e < EE) {
        int c = ei[EE + e];  // row 1 = target
        atomicAdd(&g_deg[c], ew[e]);
        atomicAdd(&g_cnt[c], 1);
    }
}

// ---------------- CSC offsets (warp scan + global cursor) + dinv ------------
__global__ void k_offs_dinv() {
    int i = blockIdx.x * blockDim.x + threadIdx.x;
    int lane = threadIdx.x & 31;
    int c = (i < NN) ? g_cnt[i] : 0;
    int v = c;
#pragma unroll
    for (int s = 1; s < 32; s <<= 1) {
        int o = __shfl_up_sync(0xffffffffu, v, s);
        if (lane >= s) v += o;
    }
    int total = __shfl_sync(0xffffffffu, v, 31);
    int base = 0;
    if (lane == 0) base = atomicAdd(&g_total, total);
    base = __shfl_sync(0xffffffffu, base, 0);
    int off = base + v - c;
    if (i < NN) {
        g_offs[i] = off;
        g_cur[i] = off;
        g_dinv[i] = rsqrtf(g_deg[i]);
    }
}

// ---------------- place edges into CSC slots (nrm precomputed) --------------
__global__ void k_place(const int* __restrict__ ei, const float* __restrict__ ew) {
    int e = blockIdx.x * blockDim.x + threadIdx.x;
    if (e >= EE) return;
    int r = ei[e];
    int c = ei[EE + e];
    int pos = atomicAdd(&g_cur[c], 1);
    float nrm = g_dinv[r] * ew[e] * g_dinv[c];
    g_edge[pos] = make_int2(r, __float_as_int(nrm));
}

// ---------------- fused gather + 16x16 linear epilogue ----------------------
__device__ __forceinline__ float* buf(int id) {
    return (id == 0) ? g_h0 : (id == 1) ? g_h1 : g_agg;
}

template <int IN, int OUT, bool BIAS_RELU>
__global__ void __launch_bounds__(256)
k_g(const float* __restrict__ W, const float* __restrict__ bias) {
    __shared__ float Wsh[HH * HH];
    __shared__ float bsh[HH];
    if (threadIdx.x < HH * HH) Wsh[threadIdx.x] = W[threadIdx.x];
    if (BIAS_RELU && threadIdx.x < HH) bsh[threadIdx.x] = bias[threadIdx.x];
    __syncthreads();

    int node = (blockIdx.x * blockDim.x + threadIdx.x) >> 5;
    if (node >= NN) return;
    int lane = threadIdx.x & 31;
    int eg = lane >> 2;   // 0..7
    int f  = lane & 3;    // float4 column 0..3
    int base = g_offs[node];
    int n = g_cnt[node];
    const float4* h = (const float4*)buf(IN);

    float ax = 0.0f, ay = 0.0f, az = 0.0f, aw = 0.0f;
    for (int i = eg; i < n; i += 8) {
        int2 e = g_edge[base + i];
        float w = __int_as_float(e.y);
        float4 t = h[(size_t)e.x * 4 + f];
        ax += t.x * w; ay += t.y * w; az += t.z * w; aw += t.w * w;
    }
#pragma unroll
    for (int s = 4; s < 32; s <<= 1) {
        ax += __shfl_xor_sync(0xffffffffu, ax, s);
        ay += __shfl_xor_sync(0xffffffffu, ay, s);
        az += __shfl_xor_sync(0xffffffffu, az, s);
        aw += __shfl_xor_sync(0xffffffffu, aw, s);
    }
    // self loop (identical value in every eg copy)
    {
        float d = g_dinv[node];
        float ws = d * d;
        float4 t = h[(size_t)node * 4 + f];
        ax += t.x * ws; ay += t.y * ws; az += t.z * ws; aw += t.w * ws;
    }
    // broadcast full 16-vector: v[4q+m] from lane q
    float v[16];
#pragma unroll
    for (int q = 0; q < 4; q++) {
        v[4 * q + 0] = __shfl_sync(0xffffffffu, ax, q);
        v[4 * q + 1] = __shfl_sync(0xffffffffu, ay, q);
        v[4 * q + 2] = __shfl_sync(0xffffffffu, az, q);
        v[4 * q + 3] = __shfl_sync(0xffffffffu, aw, q);
    }
    // epilogue matmul: lane f computes outputs 4f..4f+3
    float o0 = 0.0f, o1 = 0.0f, o2 = 0.0f, o3 = 0.0f;
#pragma unroll
    for (int k = 0; k < 16; k++) {
        const float4 w = ((const float4*)Wsh)[k * 4 + f];
        o0 += v[k] * w.x; o1 += v[k] * w.y; o2 += v[k] * w.z; o3 += v[k] * w.w;
    }
    if (BIAS_RELU) {
        o0 = fmaxf(o0 + bsh[4 * f + 0], 0.0f);
        o1 = fmaxf(o1 + bsh[4 * f + 1], 0.0f);
        o2 = fmaxf(o2 + bsh[4 * f + 2], 0.0f);
        o3 = fmaxf(o3 + bsh[4 * f + 3], 0.0f);
    }
    if (eg == 0) {
        ((float4*)buf(OUT))[(size_t)node * 4 + f] = make_float4(o0, o1, o2, o3);
    }
}

// ---------------- output layer: relu(g_agg+b2) @ W_out + b_out, log_softmax -
__global__ void k_out(const float* __restrict__ b2, const float* __restrict__ Wout,
                      const float* __restrict__ bout, float* __restrict__ out) {
    __shared__ float Wsh[HH * CC];
    __shared__ float bosh[CC];
    __shared__ float b2sh[HH];
    for (int i = threadIdx.x; i < HH * CC; i += blockDim.x) Wsh[i] = Wout[i];
    if (threadIdx.x < CC) bosh[threadIdx.x] = bout[threadIdx.x];
    if (threadIdx.x < HH) b2sh[threadIdx.x] = b2[threadIdx.x];
    __syncthreads();

    int r = blockIdx.x * blockDim.x + threadIdx.x;
    if (r >= NN) return;

    float v[16];
    const float4* ir = (const float4*)(g_agg + (size_t)r * HH);
#pragma unroll
    for (int q = 0; q < 4; q++) {
        float4 t = ir[q];
        v[4 * q] = t.x; v[4 * q + 1] = t.y; v[4 * q + 2] = t.z; v[4 * q + 3] = t.w;
    }
#pragma unroll
    for (int j = 0; j < 16; j++) v[j] = fmaxf(v[j] + b2sh[j], 0.0f);

    float lg[CC];
#pragma unroll
    for (int j = 0; j < CC; j++) lg[j] = bosh[j];
#pragma unroll
    for (int k = 0; k < 16; k++) {
        float vk = v[k];
        const float* wr = &Wsh[k * CC];
#pragma unroll
        for (int j = 0; j < CC; j++) lg[j] += vk * wr[j];
    }
    float m = lg[0];
#pragma unroll
    for (int j = 1; j < CC; j++) m = fmaxf(m, lg[j]);
    float s = 0.0f;
#pragma unroll
    for (int j = 0; j < CC; j++) s += __expf(lg[j] - m);
    float ls = __logf(s) + m;
    float* orow = out + (size_t)r * CC;
#pragma unroll
    for (int j = 0; j < CC; j++) orow[j] = lg[j] - ls;
}

// ---------------- launch: ONLY kernel launches ------------------------------
extern "C" void kernel_launch(void* const* d_in, const int* in_sizes, int n_in,
                              void* d_out, int out_size) {
    const float* x       = (const float*)d_in[0];
    const int*   ei      = (const int*)d_in[1];     // int32 (2, E) row-major
    const float* ew      = (const float*)d_in[2];
    const float* W_first = (const float*)d_in[3];
    const float* b_first = (const float*)d_in[4];
    const float* W_c1    = (const float*)d_in[5];
    const float* b_c1    = (const float*)d_in[6];
    const float* W_c2    = (const float*)d_in[7];
    const float* b_c2    = (const float*)d_in[8];
    const float* W_out   = (const float*)d_in[9];
    const float* b_out   = (const float*)d_in[10];
    float* out = (float*)d_out;

    const int TB = 256;
    int gN = (NN + TB - 1) / TB;
    int gE = (EE + TB - 1) / TB;
    int gW = (NN * 32 + TB - 1) / TB;  // warp per node

    // compact CSC build (shared by both conv layers)
    k_init<<<gN, TB>>>();
    k_deg<<<gE, TB>>>(ei, ew);
    k_offs_dinv<<<gN, TB>>>();
    k_place<<<gE, TB>>>(ei, ew);

    // fc1 -> g_h0 (16 rows per block, 2 rows per warp)
    k_fc1<<<(NN + 15) / 16, FC1_TB>>>(x, W_first, b_first);

    // conv1 fused: g_h1 = relu((A . g_h0) @ W_c1 + b_c1)
    k_g<0, 1, true><<<gW, TB>>>(W_c1, b_c1);
    // conv2 fused: g_agg = (A . g_h1) @ W_c2  (bias+relu applied in k_out)
    k_g<1, 2, false><<<gW, TB>>>(W_c2, nullptr);

    // output layer
    k_out<<<gN, TB>>>(b_c2, W_out, b_out, out);
}